// round 9
// baseline (speedup 1.0000x reference)
#include <cuda_runtime.h>
#include <math.h>

#define NV 2
#define NB 16384
#define NC 100
#define ND 512
#define ROWS_PER_WARP 2
#define ROWS_PER_BLOCK 16                        // 8 warps * 2 rows
#define BLOCKS_PER_V (NB / ROWS_PER_BLOCK)       // 1024
#define MAIN_BLOCKS (NV * BLOCKS_PER_V)          // 2048
#define TOTAL_BLOCKS (MAIN_BLOCKS + NV)          // 2050
#define COUNT_TARGET (MAIN_BLOCKS + 1)           // mains + anchor block v=1
#define MARGIN_F 10.0f

// Scratch (no dynamic allocation allowed)
__device__ float g_partials[MAIN_BLOCKS];        // per-block diff^2 partial sums
__device__ float g_inter[NV];                    // per-v inter_loss
__device__ unsigned int g_count = 0;             // completion counter

__device__ __forceinline__ void red_count_one() {
    asm volatile("red.release.gpu.global.add.u32 [%0], 1;"
                 :: "l"(&g_count) : "memory");
}

__global__ void __launch_bounds__(256) anchor_loss_fused(
    const float* __restrict__ feat,
    const int* __restrict__ label,               // int32 (JAX x64 disabled)
    const float* __restrict__ anchor,
    float* __restrict__ out)                     // out[0]=loss, out[1..]=sims
{
    if (blockIdx.x < MAIN_BLOCKS) {
        // ---- main pass: 2 rows per warp (independent chains for MLP) ----
        const int warp = threadIdx.x >> 5;
        const int lane = threadIdx.x & 31;
        const int r0   = blockIdx.x * ROWS_PER_BLOCK + warp * ROWS_PER_WARP;
        const int r1   = r0 + 1;
        const int v    = r0 >> 14;
        const int b0   = r0 & (NB - 1);
        const int b1   = r1 & (NB - 1);

        const float4* f4a = reinterpret_cast<const float4*>(feat) + (size_t)r0 * (ND / 4);
        const float4* f4b = reinterpret_cast<const float4*>(feat) + (size_t)r1 * (ND / 4);
        int l0 = min(max(__ldg(&label[b0]), 0), NC - 1);
        int l1 = min(max(__ldg(&label[b1]), 0), NC - 1);
        const float4* c4a = reinterpret_cast<const float4*>(anchor)
                            + ((size_t)v * NC + l0) * (ND / 4);
        const float4* c4b = reinterpret_cast<const float4*>(anchor)
                            + ((size_t)v * NC + l1) * (ND / 4);

        float dt0 = 0.f, fn0 = 0.f, cn0 = 0.f;
        float dt1 = 0.f, fn1 = 0.f, cn1 = 0.f;
        #pragma unroll
        for (int k = 0; k < 4; k++) {
            float4 f0 = f4a[lane + 32 * k];
            float4 f1 = f4b[lane + 32 * k];
            float4 c0 = c4a[lane + 32 * k];
            float4 c1 = c4b[lane + 32 * k];
            dt0 = fmaf(f0.x, c0.x, fmaf(f0.y, c0.y, fmaf(f0.z, c0.z, fmaf(f0.w, c0.w, dt0))));
            fn0 = fmaf(f0.x, f0.x, fmaf(f0.y, f0.y, fmaf(f0.z, f0.z, fmaf(f0.w, f0.w, fn0))));
            cn0 = fmaf(c0.x, c0.x, fmaf(c0.y, c0.y, fmaf(c0.z, c0.z, fmaf(c0.w, c0.w, cn0))));
            dt1 = fmaf(f1.x, c1.x, fmaf(f1.y, c1.y, fmaf(f1.z, c1.z, fmaf(f1.w, c1.w, dt1))));
            fn1 = fmaf(f1.x, f1.x, fmaf(f1.y, f1.y, fmaf(f1.z, f1.z, fmaf(f1.w, f1.w, fn1))));
            cn1 = fmaf(c1.x, c1.x, fmaf(c1.y, c1.y, fmaf(c1.z, c1.z, fmaf(c1.w, c1.w, cn1))));
        }
        #pragma unroll
        for (int off = 16; off > 0; off >>= 1) {
            dt0 += __shfl_xor_sync(0xffffffffu, dt0, off);
            fn0 += __shfl_xor_sync(0xffffffffu, fn0, off);
            cn0 += __shfl_xor_sync(0xffffffffu, cn0, off);
            dt1 += __shfl_xor_sync(0xffffffffu, dt1, off);
            fn1 += __shfl_xor_sync(0xffffffffu, fn1, off);
            cn1 += __shfl_xor_sync(0xffffffffu, cn1, off);
        }

        __shared__ float sh[8];
        if (lane == 0) {
            float d0 = fmaxf(sqrtf(fn0), 1e-8f) * fmaxf(sqrtf(cn0), 1e-8f);
            float d1 = fmaxf(sqrtf(fn1), 1e-8f) * fmaxf(sqrtf(cn1), 1e-8f);
            out[1 + r0] = dt0 / d0;
            out[1 + r1] = dt1 / d1;
            // sum of squared diffs: ||f||^2 - 2 f.c + ||c||^2  (both rows)
            sh[warp] = (fn0 - 2.f * dt0 + cn0) + (fn1 - 2.f * dt1 + cn1);
        }
        __syncthreads();
        if (threadIdx.x == 0) {
            float t = 0.f;
            #pragma unroll
            for (int w = 0; w < 8; w++) t += sh[w];
            g_partials[blockIdx.x] = t;
            red_count_one();             // fire-and-forget: no retirement stall
        }
        return;
    }

    // ---- anchor stats: one block per v (blockIdx 2048, 2049) ----
    const int v = blockIdx.x - MAIN_BLOCKS;
    const int t = threadIdx.x;              // 0..255, covers d and d+256
    {
        const float* a = anchor + (size_t)v * NC * ND;
        float m0 = 0.f, m1 = 0.f, s = 0.f;
        #pragma unroll 4
        for (int c = 0; c < NC; c++) {
            float x0 = a[(size_t)c * ND + t];
            float x1 = a[(size_t)c * ND + t + 256];
            m0 += x0; m1 += x1;
            s = fmaf(x0, x0, fmaf(x1, x1, s));
        }
        float q = fmaf(m0, m0, m1 * m1);

        __shared__ float shs[256], shq[256];
        shs[t] = s; shq[t] = q;
        __syncthreads();
        #pragma unroll
        for (int off = 128; off > 0; off >>= 1) {
            if (t < off) { shs[t] += shs[t + off]; shq[t] += shq[t + off]; }
            __syncthreads();
        }
        if (t == 0) {
            float S = shs[0];           // sum_c ||a_c||^2
            float M2 = shq[0];          // ||sum_c a_c||^2
            float inter = (NC * S - M2) / (float)(NC * (NC - 1));
            g_inter[v] = fmaxf(MARGIN_F - inter, 0.0f);
            if (v == 1) red_count_one();     // v=1 contributes to the count
        }
    }

    if (v != 0) return;

    // ---- block 2048 is the finalizer: poll, then deterministic reduce ----
    if (t == 0) {
        unsigned int c;
        do {
            asm volatile("ld.acquire.gpu.global.u32 %0, [%1];"
                         : "=r"(c) : "l"(&g_count));
            if (c < COUNT_TARGET) __nanosleep(64);
        } while (c < COUNT_TARGET);
    }
    __syncthreads();

    // 2048 partials as 512 float4; 256 threads * 2 float4 each. L1-bypass loads.
    const float4* p4 = reinterpret_cast<const float4*>(g_partials);
    float4 a0 = __ldcg(&p4[t]);          // v=0 range
    float4 b0 = __ldcg(&p4[t + 256]);    // v=1 range
    float t0 = (a0.x + a0.y) + (a0.z + a0.w);
    float t1 = (b0.x + b0.y) + (b0.z + b0.w);

    __shared__ float s0[256], s1[256];
    s0[t] = t0; s1[t] = t1;
    __syncthreads();
    #pragma unroll
    for (int off = 128; off > 0; off >>= 1) {
        if (t < off) { s0[t] += s0[t + off]; s1[t] += s1[t + off]; }
        __syncthreads();
    }
    if (t == 0) {
        float inter1 = __ldcg(&g_inter[1]);
        float center_mean = (s0[0] + s1[0]) / (2.0f * (float)NV * (float)NB);
        float inter_mean  = (g_inter[0] + inter1) / (float)NV;
        out[0] = center_mean + inter_mean;
        g_count = 0;                      // reset for next graph replay
    }
}

extern "C" void kernel_launch(void* const* d_in, const int* in_sizes, int n_in,
                              void* d_out, int out_size)
{
    const float* feat   = (const float*)d_in[0];
    const int*   label  = (const int*)d_in[1];
    const float* anchor = (const float*)d_in[2];
    float* out = (float*)d_out;

    anchor_loss_fused<<<TOTAL_BLOCKS, 256>>>(feat, label, anchor, out);
}

// round 10
// speedup vs baseline: 1.0592x; 1.0592x over previous
#include <cuda_runtime.h>
#include <math.h>

#define NV 2
#define NB 16384
#define NC 100
#define ND 512
#define ROWS_PER_WARP 2
#define WARPS_PER_BLOCK 16
#define ROWS_PER_BLOCK (WARPS_PER_BLOCK * ROWS_PER_WARP)   // 32
#define BLOCKS_PER_V (NB / ROWS_PER_BLOCK)                 // 512
#define MAIN_BLOCKS (NV * BLOCKS_PER_V)                    // 1024
#define MARGIN_F 10.0f

// Scratch (no dynamic allocation allowed)
__device__ float g_partials[MAIN_BLOCKS];        // per-block diff^2 partial sums
__device__ float g_inter[NV];                    // per-v inter_loss

__global__ void __launch_bounds__(512) anchor_loss_main(
    const float* __restrict__ feat,
    const int* __restrict__ label,               // int32 (JAX x64 disabled)
    const float* __restrict__ anchor,
    float* __restrict__ out)                     // out[0]=loss, out[1..]=sims
{
    if (blockIdx.x < MAIN_BLOCKS) {
        // ---- main pass: 2 rows per warp (independent chains for MLP) ----
        const int warp = threadIdx.x >> 5;
        const int lane = threadIdx.x & 31;
        const int r0   = blockIdx.x * ROWS_PER_BLOCK + warp * ROWS_PER_WARP;
        const int r1   = r0 + 1;
        const int v    = r0 >> 14;
        const int b0   = r0 & (NB - 1);
        const int b1   = r1 & (NB - 1);

        const float4* f4a = reinterpret_cast<const float4*>(feat) + (size_t)r0 * (ND / 4);
        const float4* f4b = reinterpret_cast<const float4*>(feat) + (size_t)r1 * (ND / 4);
        int l0 = min(max(__ldg(&label[b0]), 0), NC - 1);
        int l1 = min(max(__ldg(&label[b1]), 0), NC - 1);
        const float4* c4a = reinterpret_cast<const float4*>(anchor)
                            + ((size_t)v * NC + l0) * (ND / 4);
        const float4* c4b = reinterpret_cast<const float4*>(anchor)
                            + ((size_t)v * NC + l1) * (ND / 4);

        float dt0 = 0.f, fn0 = 0.f, cn0 = 0.f;
        float dt1 = 0.f, fn1 = 0.f, cn1 = 0.f;
        #pragma unroll
        for (int k = 0; k < 4; k++) {
            float4 f0 = __ldcs(&f4a[lane + 32 * k]);   // streaming: evict-first
            float4 f1 = __ldcs(&f4b[lane + 32 * k]);
            float4 c0 = c4a[lane + 32 * k];            // hot: keep cached
            float4 c1 = c4b[lane + 32 * k];
            dt0 = fmaf(f0.x, c0.x, fmaf(f0.y, c0.y, fmaf(f0.z, c0.z, fmaf(f0.w, c0.w, dt0))));
            fn0 = fmaf(f0.x, f0.x, fmaf(f0.y, f0.y, fmaf(f0.z, f0.z, fmaf(f0.w, f0.w, fn0))));
            cn0 = fmaf(c0.x, c0.x, fmaf(c0.y, c0.y, fmaf(c0.z, c0.z, fmaf(c0.w, c0.w, cn0))));
            dt1 = fmaf(f1.x, c1.x, fmaf(f1.y, c1.y, fmaf(f1.z, c1.z, fmaf(f1.w, c1.w, dt1))));
            fn1 = fmaf(f1.x, f1.x, fmaf(f1.y, f1.y, fmaf(f1.z, f1.z, fmaf(f1.w, f1.w, fn1))));
            cn1 = fmaf(c1.x, c1.x, fmaf(c1.y, c1.y, fmaf(c1.z, c1.z, fmaf(c1.w, c1.w, cn1))));
        }
        #pragma unroll
        for (int off = 16; off > 0; off >>= 1) {
            dt0 += __shfl_xor_sync(0xffffffffu, dt0, off);
            fn0 += __shfl_xor_sync(0xffffffffu, fn0, off);
            cn0 += __shfl_xor_sync(0xffffffffu, cn0, off);
            dt1 += __shfl_xor_sync(0xffffffffu, dt1, off);
            fn1 += __shfl_xor_sync(0xffffffffu, fn1, off);
            cn1 += __shfl_xor_sync(0xffffffffu, cn1, off);
        }

        __shared__ float sh[WARPS_PER_BLOCK];
        if (lane == 0) {
            float d0 = fmaxf(sqrtf(fn0), 1e-8f) * fmaxf(sqrtf(cn0), 1e-8f);
            float d1 = fmaxf(sqrtf(fn1), 1e-8f) * fmaxf(sqrtf(cn1), 1e-8f);
            __stcs(&out[1 + r0], dt0 / d0);
            __stcs(&out[1 + r1], dt1 / d1);
            // sum of squared diffs: ||f||^2 - 2 f.c + ||c||^2  (both rows)
            sh[warp] = (fn0 - 2.f * dt0 + cn0) + (fn1 - 2.f * dt1 + cn1);
        }
        __syncthreads();
        if (threadIdx.x == 0) {
            float t = 0.f;
            #pragma unroll
            for (int w = 0; w < WARPS_PER_BLOCK; w++) t += sh[w];
            g_partials[blockIdx.x] = t;
        }
    } else {
        // ---- anchor stats: one block per v (512 threads = one per d) ----
        // pair_sum = C * sum_c ||a_c||^2 - ||sum_c a_c||^2 (pd diagonal is 0)
        const int v = blockIdx.x - MAIN_BLOCKS;
        const int t = threadIdx.x;          // 0..511 = d index
        const float* a = anchor + (size_t)v * NC * ND;

        float m = 0.f, s = 0.f;
        #pragma unroll 4
        for (int c = 0; c < NC; c++) {
            float x = a[(size_t)c * ND + t];
            m += x;
            s = fmaf(x, x, s);
        }
        float q = m * m;

        __shared__ float shs[512], shq[512];
        shs[t] = s; shq[t] = q;
        __syncthreads();
        #pragma unroll
        for (int off = 256; off > 0; off >>= 1) {
            if (t < off) { shs[t] += shs[t + off]; shq[t] += shq[t + off]; }
            __syncthreads();
        }
        if (t == 0) {
            float S = shs[0];          // sum_c ||a_c||^2
            float M2 = shq[0];         // ||sum_c a_c||^2
            float inter = (NC * S - M2) / (float)(NC * (NC - 1));
            g_inter[v] = fmaxf(MARGIN_F - inter, 0.0f);
        }
    }
}

__global__ void __launch_bounds__(256) anchor_loss_finalize(float* __restrict__ out)
{
    const int t = threadIdx.x;  // 256 threads; 512 partials per v
    float t0 = g_partials[t] + g_partials[t + 256];                    // v = 0
    float t1 = g_partials[BLOCKS_PER_V + t] + g_partials[BLOCKS_PER_V + t + 256]; // v=1

    __shared__ float s0[256], s1[256];
    s0[t] = t0; s1[t] = t1;
    __syncthreads();
    #pragma unroll
    for (int off = 128; off > 0; off >>= 1) {
        if (t < off) { s0[t] += s0[t + off]; s1[t] += s1[t + off]; }
        __syncthreads();
    }
    if (t == 0) {
        float center_mean = (s0[0] + s1[0]) / (2.0f * (float)NV * (float)NB);
        float inter_mean  = (g_inter[0] + g_inter[1]) / (float)NV;
        out[0] = center_mean + inter_mean;
    }
}

extern "C" void kernel_launch(void* const* d_in, const int* in_sizes, int n_in,
                              void* d_out, int out_size)
{
    const float* feat   = (const float*)d_in[0];
    const int*   label  = (const int*)d_in[1];
    const float* anchor = (const float*)d_in[2];
    float* out = (float*)d_out;

    anchor_loss_main<<<MAIN_BLOCKS + NV, 512>>>(feat, label, anchor, out);
    anchor_loss_finalize<<<1, 256>>>(out);
}